// round 2
// baseline (speedup 1.0000x reference)
#include <cuda_runtime.h>

#define EPS 1e-8f

// Problem dims (fixed by the dataset)
constexpr int NI   = 64;    // images
constexpr int NR   = 36;    // regions
constexpr int D    = 1024;  // embed dim
constexpr int NC   = 64;    // captions
constexpr int LMAX = 40;    // max words
constexpr int NBK  = 32;    // num_block

constexpr int CAPS_PER_BLK = 4;

// SMEM strides (floats); keep rows 16B-aligned for float4
constexpr int IMG_STR = 1028;  // 1024 + 4 pad
constexpr int CAP_STR = 260;   // 256 + 4 pad
constexpr int ATT_STR = 41;
constexpr int A_STR   = 37;
constexpr int COS_STR = 33;

// SMEM layout offsets (in floats)
constexpr int OFF_IMG = 0;
constexpr int OFF_CAP = OFF_IMG + NR * IMG_STR;     // 37008
constexpr int OFF_ATT = OFF_CAP + LMAX * CAP_STR;   // +10400
constexpr int OFF_A   = OFF_ATT + NR * ATT_STR;     // +1476
constexpr int OFF_COS = OFF_A + LMAX * A_STR;       // +1480
constexpr int OFF_W1  = OFF_COS + LMAX * COS_STR;   // +1320
constexpr int OFF_B1  = OFF_W1 + 8 * 32;
constexpr int OFF_W2S = OFF_B1 + 8;
constexpr int OFF_RED = OFF_W2S + 8;
constexpr int OFF_B2S = OFF_RED + 64;
constexpr int SMEM_FLOATS = OFF_B2S + 1;
constexpr int SMEM_BYTES  = SMEM_FLOATS * 4;        // ~208 KB

__device__ __forceinline__ void fma4(float& acc, const float4& a, const float4& b) {
    acc = fmaf(a.x, b.x, acc);
    acc = fmaf(a.y, b.y, acc);
    acc = fmaf(a.z, b.z, acc);
    acc = fmaf(a.w, b.w, acc);
}

__global__ __launch_bounds__(256, 1)
void tg_kernel(const float* __restrict__ images, const float* __restrict__ captions,
               const int* __restrict__ cap_lens, const float* __restrict__ rare,
               const float* __restrict__ v1, const float* __restrict__ g1, const float* __restrict__ b1,
               const float* __restrict__ v2, const float* __restrict__ g2, const float* __restrict__ b2,
               const int* __restrict__ lam_p, float* __restrict__ out)
{
    extern __shared__ float sm[];
    const int tid = threadIdx.x;
    const int img = blockIdx.x;
    const int c0  = blockIdx.y * CAPS_PER_BLK;

    // ---- Preamble: image tile -> SMEM (reused across 4 captions x 2 passes) ----
    {
        const float4* gsrc = (const float4*)(images + (size_t)img * NR * D);
        for (int idx = tid; idx < NR * (D / 4); idx += 256) {
            int r = idx >> 8, k4 = idx & 255;
            *((float4*)(sm + OFF_IMG + r * IMG_STR) + k4) = gsrc[r * (D / 4) + k4];
        }
    }
    // weight-normed MLP params (tiny, once per block)
    if (tid < 8) {
        int j = tid;
        float s = 0.f;
        for (int n = 0; n < 32; n++) { float v = v1[j * 32 + n]; s += v * v; }
        float inv = g1[j] / sqrtf(s);
        for (int n = 0; n < 32; n++) sm[OFF_W1 + j * 32 + n] = v1[j * 32 + n] * inv;
        sm[OFF_B1 + j] = b1[j];
    }
    if (tid == 8) {
        float w2s[8] = {0, 0, 0, 0, 0, 0, 0, 0};
        float b2s = 0.f;
        for (int k = 0; k < 6; k++) {
            float s = 0.f;
            for (int j = 0; j < 8; j++) { float v = v2[k * 8 + j]; s += v * v; }
            float inv = g2[k] / sqrtf(s);
            for (int j = 0; j < 8; j++) w2s[j] += v2[k * 8 + j] * inv;
            b2s += b2[k];
        }
        for (int j = 0; j < 8; j++) sm[OFF_W2S + j] = w2s[j];
        sm[OFF_B2S] = b2s;
    }
    const float lam = (float)(*lam_p);
    __syncthreads();

    for (int cc = c0; cc < c0 + CAPS_PER_BLK; cc++) {
        const int len = cap_lens[cc];
        const float* capg = captions + (size_t)cc * LMAX * D;

        // ================= Phase A: S[r][l] = img[r,:] . cap[l,:] =================
        float acc[3][2] = {};
        const int tr = tid / 20, tl = tid % 20;
        const int r0 = tr * 3;
        const bool act = (tid < 240);

        for (int kc = 0; kc < 4; kc++) {
            // stream caption chunk [40 x 256] into SMEM
            for (int idx = tid; idx < LMAX * 64; idx += 256) {
                int l = idx >> 6, k4 = idx & 63;
                *((float4*)(sm + OFF_CAP + l * CAP_STR) + k4) =
                    *((const float4*)(capg + (size_t)l * D + kc * 256) + k4);
            }
            __syncthreads();
            if (act) {
                const float4* i0 = (const float4*)(sm + OFF_IMG + (r0 + 0) * IMG_STR) + kc * 64;
                const float4* i1 = (const float4*)(sm + OFF_IMG + (r0 + 1) * IMG_STR) + kc * 64;
                const float4* i2 = (const float4*)(sm + OFF_IMG + (r0 + 2) * IMG_STR) + kc * 64;
                const float4* ca = (const float4*)(sm + OFF_CAP + tl * CAP_STR);
                const float4* cb = (const float4*)(sm + OFF_CAP + (tl + 20) * CAP_STR);
                #pragma unroll 8
                for (int k4 = 0; k4 < 64; k4++) {
                    float4 a0 = i0[k4], a1 = i1[k4], a2 = i2[k4];
                    float4 x = ca[k4], y = cb[k4];
                    fma4(acc[0][0], a0, x); fma4(acc[0][1], a0, y);
                    fma4(acc[1][0], a1, x); fma4(acc[1][1], a1, y);
                    fma4(acc[2][0], a2, x); fma4(acc[2][1], a2, y);
                }
            }
            __syncthreads();
        }
        // leaky-relu(0.1) * word-mask, write S to SMEM
        if (act) {
            #pragma unroll
            for (int a = 0; a < 3; a++) {
                #pragma unroll
                for (int b = 0; b < 2; b++) {
                    int l = tl + b * 20;
                    float v = acc[a][b];
                    v = v > 0.f ? v : 0.1f * v;
                    sm[OFF_ATT + (r0 + a) * ATT_STR + l] = (l < len) ? v : 0.f;
                }
            }
        }
        __syncthreads();

        // ===== Phase B1: l2 norm over words, per region =====
        if (tid < NR) {
            float* row = sm + OFF_ATT + tid * ATT_STR;
            float s = 0.f;
            for (int l = 0; l < LMAX; l++) { float v = row[l]; s += v * v; }
            float inv = 1.f / (sqrtf(s) + EPS);
            for (int l = 0; l < LMAX; l++) row[l] *= inv;
        }
        __syncthreads();

        // ===== Phase B2: softmax over regions per word (store transposed A[l][r]) =====
        if (tid < LMAX) {
            const int l = tid;
            float mx = -1e30f;
            for (int r = 0; r < NR; r++) {
                float v = sm[OFF_ATT + r * ATT_STR + l] * lam;
                mx = fmaxf(mx, v);
            }
            float s = 0.f;
            for (int r = 0; r < NR; r++) {
                float e = __expf(sm[OFF_ATT + r * ATT_STR + l] * lam - mx);
                sm[OFF_A + l * A_STR + r] = e;
                s += e;
            }
            float inv = 1.f / s;
            for (int r = 0; r < NR; r++) sm[OFF_A + l * A_STR + r] *= inv;
        }
        __syncthreads();

        // ===== Phase C: wctx = A . img (on the fly), block-cosine vs cap =====
        for (int kc = 0; kc < 4; kc++) {
            for (int idx = tid; idx < LMAX * 64; idx += 256) {
                int l = idx >> 6, k4 = idx & 63;
                *((float4*)(sm + OFF_CAP + l * CAP_STR) + k4) =
                    *((const float4*)(capg + (size_t)l * D + kc * 256) + k4);
            }
            __syncthreads();
            const int items = len * 8;  // valid words x 8 n-blocks in this chunk
            for (int it = tid; it < items; it += 256) {
                const int l = it % len;     // fastest -> img loads broadcast across warp
                const int nbl = it / len;
                const float* arow = sm + OFF_A + l * A_STR;
                float4 w[8];
                #pragma unroll
                for (int b = 0; b < 8; b++) w[b] = make_float4(0.f, 0.f, 0.f, 0.f);
                #pragma unroll 4
                for (int r = 0; r < NR; r++) {
                    float a = arow[r];
                    const float4* ip = (const float4*)(sm + OFF_IMG + r * IMG_STR) + kc * 64 + nbl * 8;
                    #pragma unroll
                    for (int b = 0; b < 8; b++) {
                        float4 iv = ip[b];
                        w[b].x = fmaf(a, iv.x, w[b].x);
                        w[b].y = fmaf(a, iv.y, w[b].y);
                        w[b].z = fmaf(a, iv.z, w[b].z);
                        w[b].w = fmaf(a, iv.w, w[b].w);
                    }
                }
                float w12 = 0.f, cn2 = 0.f, qn2 = 0.f;
                const float4* cp = (const float4*)(sm + OFF_CAP + l * CAP_STR) + nbl * 8;
                #pragma unroll
                for (int b = 0; b < 8; b++) {
                    float4 q = cp[b];
                    w12 += w[b].x * q.x + w[b].y * q.y + w[b].z * q.z + w[b].w * q.w;
                    cn2 += w[b].x * w[b].x + w[b].y * w[b].y + w[b].z * w[b].z + w[b].w * w[b].w;
                    qn2 += q.x * q.x + q.y * q.y + q.z * q.z + q.w * q.w;
                }
                float denom = fmaxf(sqrtf(cn2) * sqrtf(qn2), EPS);
                sm[OFF_COS + l * COS_STR + kc * 8 + nbl] = w12 / denom;
            }
            __syncthreads();
        }

        // ===== Phase D: weight-normed MLP + masked mean =====
        if (tid < 64) sm[OFF_RED + tid] = 0.f;
        __syncthreads();
        if (tid < len) {
            const int l = tid;
            const float* rr = rare + ((size_t)cc * LMAX + l) * NBK;
            float x[32];
            #pragma unroll
            for (int n = 0; n < 32; n++)
                x[n] = sm[OFF_COS + l * COS_STR + n] + 0.4f * rr[n];
            float persum = sm[OFF_B2S];
            #pragma unroll
            for (int j = 0; j < 8; j++) {
                float h = sm[OFF_B1 + j];
                const float* wr = sm + OFF_W1 + j * 32;
                #pragma unroll
                for (int n = 0; n < 32; n++) h = fmaf(x[n], wr[n], h);
                persum = fmaf(tanhf(h), sm[OFF_W2S + j], persum);
            }
            sm[OFF_RED + l] = persum;
        }
        __syncthreads();
        if (tid == 0) {
            float s = 0.f;
            for (int l = 0; l < len; l++) s += sm[OFF_RED + l];
            out[(size_t)img * NC + cc] = s / (float)(len * 6);
        }
        __syncthreads();
    }
}

extern "C" void kernel_launch(void* const* d_in, const int* in_sizes, int n_in,
                              void* d_out, int out_size) {
    const float* images   = (const float*)d_in[0];
    const float* captions = (const float*)d_in[1];
    const int*   cap_lens = (const int*)d_in[2];
    const float* rare     = (const float*)d_in[3];
    const float* v1       = (const float*)d_in[4];
    const float* g1       = (const float*)d_in[5];
    const float* b1       = (const float*)d_in[6];
    const float* v2       = (const float*)d_in[7];
    const float* g2       = (const float*)d_in[8];
    const float* b2       = (const float*)d_in[9];
    const int*   lam      = (const int*)d_in[12];
    float* out = (float*)d_out;

    cudaFuncSetAttribute(tg_kernel, cudaFuncAttributeMaxDynamicSharedMemorySize, SMEM_BYTES);
    tg_kernel<<<dim3(NI, NC / CAPS_PER_BLK, 1), 256, SMEM_BYTES>>>(
        images, captions, cap_lens, rare, v1, g1, b1, v2, g2, b2, lam, out);
}

// round 3
// speedup vs baseline: 1.1878x; 1.1878x over previous
#include <cuda_runtime.h>

#define EPS 1e-8f
typedef unsigned long long ull;

constexpr int NI = 64, NR = 36, D = 1024, NC = 64, LMAX = 40, NBK = 32;

constexpr int CAP_STR = 132;  // floats per caption row chunk (128 data + 4 pad)
constexpr int ATT_STR = 41, A_STR = 37, COS_STR = 33;

constexpr int OFF_IMG = 0;                 // 36*1024 = 36864 (no pad; reads are broadcast)
constexpr int OFF_CAP = 36864;             // 2 caps * 40 * 132 = 10560
constexpr int OFF_ATT = OFF_CAP + 10560;   // 2 * 36*41 = 2952
constexpr int OFF_A   = OFF_ATT + 2952;    // 2 * 40*37 = 2960
constexpr int OFF_COS = OFF_A + 2960;      // 2 * 40*33 = 2640
constexpr int OFF_W1  = OFF_COS + 2640;    // 256
constexpr int OFF_B1  = OFF_W1 + 256;      // 8
constexpr int OFF_W2S = OFF_B1 + 8;        // 8
constexpr int OFF_B2S = OFF_W2S + 8;       // 1
constexpr int OFF_RED = OFF_B2S + 1;       // 80
constexpr int SMEM_FLOATS = OFF_RED + 80;
constexpr int SMEM_BYTES  = SMEM_FLOATS * 4;   // ~225.3 KB

// ---- packed f32x2 helpers (ptxas never emits FFMA2 from C++; PTX only) ----
__device__ __forceinline__ ull pk(float a, float b) {
    ull r; asm("mov.b64 %0, {%1, %2};" : "=l"(r) : "f"(a), "f"(b)); return r;
}
__device__ __forceinline__ ull dup2(float a) {
    ull r; asm("mov.b64 %0, {%1, %1};" : "=l"(r) : "f"(a)); return r;
}
__device__ __forceinline__ void f2(ull& d, ull a, ull b) {
    asm("fma.rn.f32x2 %0, %1, %2, %0;" : "+l"(d) : "l"(a), "l"(b));
}
__device__ __forceinline__ void up(ull v, float& lo, float& hi) {
    asm("mov.b64 {%0, %1}, %2;" : "=f"(lo), "=f"(hi) : "l"(v));
}

__global__ __launch_bounds__(256, 1)
void tg_kernel(const float* __restrict__ images, const float* __restrict__ captions,
               const int* __restrict__ cap_lens, const float* __restrict__ rare,
               const float* __restrict__ v1, const float* __restrict__ g1, const float* __restrict__ b1,
               const float* __restrict__ v2, const float* __restrict__ g2, const float* __restrict__ b2,
               const int* __restrict__ lam_p, float* __restrict__ out)
{
    extern __shared__ float sm[];
    const int tid = threadIdx.x;
    const int img = blockIdx.x;
    const int c0  = blockIdx.y * 4;

    // ---- image tile -> SMEM (linear copy, reused by everything) ----
    {
        const float4* gsrc = (const float4*)(images + (size_t)img * NR * D);
        float4* dst = (float4*)sm;
        for (int i = tid; i < NR * (D / 4); i += 256) dst[i] = gsrc[i];
    }
    // ---- weight-normed MLP params ----
    if (tid < 8) {
        int j = tid;
        float s = 0.f;
        for (int n = 0; n < 32; n++) { float v = v1[j * 32 + n]; s += v * v; }
        float inv = g1[j] / sqrtf(s);
        for (int n = 0; n < 32; n++) sm[OFF_W1 + j * 32 + n] = v1[j * 32 + n] * inv;
        sm[OFF_B1 + j] = b1[j];
    }
    if (tid == 8) {
        float w2s[8] = {0,0,0,0,0,0,0,0}; float b2s = 0.f;
        for (int k = 0; k < 6; k++) {
            float s = 0.f;
            for (int j = 0; j < 8; j++) { float v = v2[k * 8 + j]; s += v * v; }
            float inv = g2[k] / sqrtf(s);
            for (int j = 0; j < 8; j++) w2s[j] += v2[k * 8 + j] * inv;
            b2s += b2[k];
        }
        for (int j = 0; j < 8; j++) sm[OFF_W2S + j] = w2s[j];
        sm[OFF_B2S] = b2s;
    }
    const float lam = (float)(*lam_p);
    __syncthreads();

    // thread map for phase A: cap_i in [0,2), rg in [0,6), lg in [0,20)
    const int cap_i = tid / 120;
    const int rem   = tid % 120;
    const int rg    = rem / 20;
    const int lg    = rem % 20;
    const int r0    = rg * 6;
    const bool actA = (tid < 240);

    for (int pair = 0; pair < 2; pair++) {
        const int cA = c0 + pair * 2;
        const int len0 = cap_lens[cA];
        const int len1 = cap_lens[cA + 1];
        const int lenMy = cap_i ? len1 : len0;

        // ========== Phase A: S[r][l] = img[r,:].cap[l,:], FFMA2 over region-pairs ==========
        ull acc00 = 0, acc01 = 0, acc10 = 0, acc11 = 0, acc20 = 0, acc21 = 0;
        const float4* ib0 = (const float4*)sm + (r0 + 0) * 256;
        const float4* ib1 = (const float4*)sm + (r0 + 1) * 256;
        const float4* ib2 = (const float4*)sm + (r0 + 2) * 256;
        const float4* ib3 = (const float4*)sm + (r0 + 3) * 256;
        const float4* ib4 = (const float4*)sm + (r0 + 4) * 256;
        const float4* ib5 = (const float4*)sm + (r0 + 5) * 256;
        const float4* cap4 = (const float4*)(sm + OFF_CAP + (cap_i * 40 + lg) * CAP_STR);
        const float4* cbp4 = (const float4*)(sm + OFF_CAP + (cap_i * 40 + lg + 20) * CAP_STR);

        for (int ch = 0; ch < 8; ch++) {
            // stream 2 captions x 40 rows x 128 floats of this chunk
            for (int idx = tid; idx < 2 * 40 * 32; idx += 256) {
                int ci = idx / 1280, r2 = idx % 1280, l = r2 / 32, k4 = r2 % 32;
                ((float4*)(sm + OFF_CAP + (ci * 40 + l) * CAP_STR))[k4] =
                    ((const float4*)(captions + (size_t)(cA + ci) * LMAX * D + l * D + ch * 128))[k4];
            }
            __syncthreads();
            if (actA) {
                const int kb = ch * 32;
                #pragma unroll 4
                for (int k4 = 0; k4 < 32; k4++) {
                    float4 i0 = ib0[kb + k4], i1 = ib1[kb + k4], i2 = ib2[kb + k4];
                    float4 i3 = ib3[kb + k4], i4 = ib4[kb + k4], i5 = ib5[kb + k4];
                    float4 x = cap4[k4], y = cbp4[k4];
                    #define STEP(CMP) { \
                        ull a01 = pk(i0.CMP, i1.CMP), a23 = pk(i2.CMP, i3.CMP), a45 = pk(i4.CMP, i5.CMP); \
                        ull bx = dup2(x.CMP), by = dup2(y.CMP); \
                        f2(acc00, a01, bx); f2(acc01, a01, by); \
                        f2(acc10, a23, bx); f2(acc11, a23, by); \
                        f2(acc20, a45, bx); f2(acc21, a45, by); }
                    STEP(x) STEP(y) STEP(z) STEP(w)
                    #undef STEP
                }
            }
            __syncthreads();
        }
        // epilogue: unpack, leaky-relu, word mask, store S
        if (actA) {
            float* base = sm + OFF_ATT + cap_i * (NR * ATT_STR);
            const int l0 = lg, l1 = lg + 20;
            const float m0 = (l0 < lenMy) ? 1.f : 0.f;
            const float m1 = (l1 < lenMy) ? 1.f : 0.f;
            ull accs[3][2] = {{acc00, acc01}, {acc10, acc11}, {acc20, acc21}};
            #pragma unroll
            for (int i = 0; i < 3; i++) {
                float lo, hi;
                up(accs[i][0], lo, hi);
                lo = (lo > 0.f ? lo : 0.1f * lo) * m0;
                hi = (hi > 0.f ? hi : 0.1f * hi) * m0;
                base[(r0 + 2 * i) * ATT_STR + l0] = lo;
                base[(r0 + 2 * i + 1) * ATT_STR + l0] = hi;
                up(accs[i][1], lo, hi);
                lo = (lo > 0.f ? lo : 0.1f * lo) * m1;
                hi = (hi > 0.f ? hi : 0.1f * hi) * m1;
                base[(r0 + 2 * i) * ATT_STR + l1] = lo;
                base[(r0 + 2 * i + 1) * ATT_STR + l1] = hi;
            }
        }
        __syncthreads();

        // ========== Phase B1: l2 norm over words per region ==========
        if (tid < 72) {
            int ci = tid / 36, r = tid % 36;
            float* row = sm + OFF_ATT + ci * (NR * ATT_STR) + r * ATT_STR;
            float s = 0.f;
            #pragma unroll 8
            for (int l = 0; l < LMAX; l++) { float v = row[l]; s += v * v; }
            float inv = 1.f / (sqrtf(s) + EPS);
            #pragma unroll 8
            for (int l = 0; l < LMAX; l++) row[l] *= inv;
        }
        __syncthreads();

        // ========== Phase B2: softmax over regions per valid word ==========
        if (tid < 80) {
            int ci = tid / 40, l = tid % 40;
            int len = ci ? len1 : len0;
            if (l < len) {
                const float* Sb = sm + OFF_ATT + ci * (NR * ATT_STR);
                float* Ar = sm + OFF_A + ci * (LMAX * A_STR) + l * A_STR;
                float s = 0.f;
                #pragma unroll 4
                for (int r = 0; r < NR; r++) {
                    float e = __expf(Sb[r * ATT_STR + l] * lam);  // |x|<=20: safe w/o max-sub
                    Ar[r] = e; s += e;
                }
                float inv = 1.f / s;
                #pragma unroll 4
                for (int r = 0; r < NR; r++) Ar[r] *= inv;
            }
        }
        __syncthreads();

        // ========== Phase C: wctx + block cosine (FFMA2, 2 words per thread) ==========
        for (int ci = 0; ci < 2; ci++) {
            const int len = ci ? len1 : len0;
            const int hl = (len + 1) >> 1;
            const int items = 32 * hl;
            const float* Ab = sm + OFF_A + ci * (LMAX * A_STR);
            const float* capgl = captions + (size_t)(cA + ci) * LMAX * D;
            for (int it = tid; it < items; it += 256) {
                const int nbl = it / hl;
                const int l0i = it - nbl * hl;
                const int l1i = l0i + hl;
                const bool has1 = (l1i < len);
                const float* a0r = Ab + l0i * A_STR;
                const float* a1r = Ab + (has1 ? l1i : l0i) * A_STR;
                ull w0[16], w1[16];
                #pragma unroll
                for (int b = 0; b < 16; b++) { w0[b] = 0ull; w1[b] = 0ull; }
                #pragma unroll 4
                for (int r = 0; r < NR; r++) {
                    ull a0d = dup2(a0r[r]);
                    ull a1d = dup2(a1r[r]);
                    const ulonglong2* ip = (const ulonglong2*)(sm + r * D + nbl * 32);
                    #pragma unroll
                    for (int b = 0; b < 8; b++) {
                        ulonglong2 iv = ip[b];
                        f2(w0[2 * b], a0d, iv.x); f2(w0[2 * b + 1], a0d, iv.y);
                        f2(w1[2 * b], a1d, iv.x); f2(w1[2 * b + 1], a1d, iv.y);
                    }
                }
                // cosine for l0
                {
                    const float4* q4 = (const float4*)(capgl + l0i * D + nbl * 32);
                    float w12 = 0.f, cn2 = 0.f, qn2 = 0.f;
                    #pragma unroll
                    for (int b = 0; b < 8; b++) {
                        float4 q = q4[b]; float wx, wy, wz, ww;
                        up(w0[2 * b], wx, wy); up(w0[2 * b + 1], wz, ww);
                        w12 += wx * q.x + wy * q.y + wz * q.z + ww * q.w;
                        cn2 += wx * wx + wy * wy + wz * wz + ww * ww;
                        qn2 += q.x * q.x + q.y * q.y + q.z * q.z + q.w * q.w;
                    }
                    sm[OFF_COS + ci * (LMAX * COS_STR) + l0i * COS_STR + nbl] =
                        w12 / fmaxf(sqrtf(cn2) * sqrtf(qn2), EPS);
                }
                if (has1) {
                    const float4* q4 = (const float4*)(capgl + l1i * D + nbl * 32);
                    float w12 = 0.f, cn2 = 0.f, qn2 = 0.f;
                    #pragma unroll
                    for (int b = 0; b < 8; b++) {
                        float4 q = q4[b]; float wx, wy, wz, ww;
                        up(w1[2 * b], wx, wy); up(w1[2 * b + 1], wz, ww);
                        w12 += wx * q.x + wy * q.y + wz * q.z + ww * q.w;
                        cn2 += wx * wx + wy * wy + wz * wz + ww * ww;
                        qn2 += q.x * q.x + q.y * q.y + q.z * q.z + q.w * q.w;
                    }
                    sm[OFF_COS + ci * (LMAX * COS_STR) + l1i * COS_STR + nbl] =
                        w12 / fmaxf(sqrtf(cn2) * sqrtf(qn2), EPS);
                }
            }
        }
        __syncthreads();

        // ========== Phase D: MLP + masked mean ==========
        if (tid < 80) {
            int ci = tid / 40, l = tid % 40;
            int len = ci ? len1 : len0;
            float res = 0.f;
            if (l < len) {
                const float* rr = rare + ((size_t)(cA + ci) * LMAX + l) * NBK;
                const float* cb = sm + OFF_COS + ci * (LMAX * COS_STR) + l * COS_STR;
                float x[32];
                #pragma unroll
                for (int n = 0; n < 32; n++) x[n] = cb[n] + 0.4f * rr[n];
                float persum = sm[OFF_B2S];
                #pragma unroll
                for (int j = 0; j < 8; j++) {
                    float h = sm[OFF_B1 + j];
                    const float* wr = sm + OFF_W1 + j * 32;
                    #pragma unroll
                    for (int n = 0; n < 32; n++) h = fmaf(x[n], wr[n], h);
                    persum = fmaf(tanhf(h), sm[OFF_W2S + j], persum);
                }
                res = persum;
            }
            sm[OFF_RED + tid] = res;
        }
        __syncthreads();
        if (tid < 2) {
            int len = tid ? len1 : len0;
            float s = 0.f;
            for (int l = 0; l < len; l++) s += sm[OFF_RED + tid * 40 + l];
            out[(size_t)img * NC + (cA + tid)] = s / (float)(len * 6);
        }
        __syncthreads();
    }
}

extern "C" void kernel_launch(void* const* d_in, const int* in_sizes, int n_in,
                              void* d_out, int out_size) {
    const float* images   = (const float*)d_in[0];
    const float* captions = (const float*)d_in[1];
    const int*   cap_lens = (const int*)d_in[2];
    const float* rare     = (const float*)d_in[3];
    const float* v1       = (const float*)d_in[4];
    const float* g1       = (const float*)d_in[5];
    const float* b1       = (const float*)d_in[6];
    const float* v2       = (const float*)d_in[7];
    const float* g2       = (const float*)d_in[8];
    const float* b2       = (const float*)d_in[9];
    const int*   lam      = (const int*)d_in[12];
    float* out = (float*)d_out;

    cudaFuncSetAttribute(tg_kernel, cudaFuncAttributeMaxDynamicSharedMemorySize, SMEM_BYTES);
    tg_kernel<<<dim3(NI, NC / 4, 1), 256, SMEM_BYTES>>>(
        images, captions, cap_lens, rare, v1, g1, b1, v2, g2, b2, lam, out);
}

// round 4
// speedup vs baseline: 1.4878x; 1.2525x over previous
#include <cuda_runtime.h>

#define EPS 1e-8f
typedef unsigned long long ull;

constexpr int D = 1024, LMAX = 40, NRG = 36;
constexpr int IST = 1090;            // img2 row stride (ull): 1024 + 64 skew + 2 pad
constexpr int CAP_ROW = 68;          // chunk row stride (floats): 64 + 4
constexpr int CAP_CAP = 2728;        // per-cap chunk stride (floats): 40*68 + 8

// float offsets
constexpr int OFF_R   = 39240;       // = 18*1090*8/4 : end of img2 region
constexpr int OFF_ATT = OFF_R;                  // [cap][r*41+l], 4*1476 = 5904 floats
constexpr int OFF_A2F = OFF_R + 5904;           // packed attn, ull area: 4*756 ull = 6048 floats
constexpr int OFF_COS = OFF_R;                  // reuses ATT after B2: [cap][l*33+nbl]
constexpr int OFF_W1  = OFF_R + 5904 + 6048;    // 51192
constexpr int OFF_B1  = OFF_W1 + 256;
constexpr int OFF_W2S = OFF_B1 + 8;
constexpr int OFF_B2S = OFF_W2S + 8;
constexpr int OFF_RED = OFF_B2S + 4;            // 51468
constexpr int SMEM_FLOATS = OFF_RED + 160;
constexpr int SMEM_BYTES  = SMEM_FLOATS * 4;    // ~206.5 KB

__device__ __forceinline__ ull pk(float a, float b) {
    ull r; asm("mov.b64 %0, {%1, %2};" : "=l"(r) : "f"(a), "f"(b)); return r;
}
__device__ __forceinline__ ull dup2(float a) {
    ull r; asm("mov.b64 %0, {%1, %1};" : "=l"(r) : "f"(a)); return r;
}
__device__ __forceinline__ void f2(ull& d, ull a, ull b) {
    asm("fma.rn.f32x2 %0, %1, %2, %0;" : "+l"(d) : "l"(a), "l"(b));
}
__device__ __forceinline__ void up(ull v, float& lo, float& hi) {
    asm("mov.b64 {%0, %1}, %2;" : "=f"(lo), "=f"(hi) : "l"(v));
}

__global__ __launch_bounds__(256, 1)
void tg_kernel(const float* __restrict__ images, const float* __restrict__ captions,
               const int* __restrict__ cap_lens, const float* __restrict__ rare,
               const float* __restrict__ v1, const float* __restrict__ g1, const float* __restrict__ b1,
               const float* __restrict__ v2, const float* __restrict__ g2, const float* __restrict__ b2,
               const int* __restrict__ lam_p, float* __restrict__ out)
{
    extern __shared__ float sm[];
    ull* smu = (ull*)sm;
    const int tid = threadIdx.x;
    const int img = blockIdx.x;
    const int c0  = blockIdx.y * 4;

    // ---- preamble: image -> SMEM, region-pair interleaved + 32-d skew ----
    {
        const float4* g4 = (const float4*)(images + (size_t)img * NRG * D);
        for (int i = tid; i < 9216; i += 256) {
            int r = i >> 8, k = (i & 255) * 4;
            float4 v = g4[i];
            int ub = (r >> 1) * IST + k + 2 * (k >> 5);
            int fb = 2 * ub + (r & 1);
            sm[fb] = v.x; sm[fb + 2] = v.y; sm[fb + 4] = v.z; sm[fb + 6] = v.w;
        }
    }
    if (tid < 8) {
        int j = tid; float s = 0.f;
        for (int n = 0; n < 32; n++) { float v = v1[j * 32 + n]; s += v * v; }
        float inv = g1[j] / sqrtf(s);
        for (int n = 0; n < 32; n++) sm[OFF_W1 + j * 32 + n] = v1[j * 32 + n] * inv;
        sm[OFF_B1 + j] = b1[j];
    }
    if (tid == 8) {
        float w2s[8] = {0,0,0,0,0,0,0,0}; float b2s = 0.f;
        for (int k = 0; k < 6; k++) {
            float s = 0.f;
            for (int j = 0; j < 8; j++) { float v = v2[k * 8 + j]; s += v * v; }
            float inv = g2[k] / sqrtf(s);
            for (int j = 0; j < 8; j++) w2s[j] += v2[k * 8 + j] * inv;
            b2s += b2[k];
        }
        for (int j = 0; j < 8; j++) sm[OFF_W2S + j] = w2s[j];
        sm[OFF_B2S] = b2s;
    }
    const float lam = (float)(*lam_p);

    // Phase A thread map: khalf (k-split) x [cap][lg][rg], rg fastest in warp
    const int khalf = tid / 120, t2 = tid % 120;
    const int capi = t2 / 30, remA = t2 % 30, lg = remA / 6, rg = remA % 6;
    const bool actA = (tid < 240);

    ull acc[3][8];
    #pragma unroll
    for (int p = 0; p < 3; p++)
        #pragma unroll
        for (int j = 0; j < 8; j++) acc[p][j] = 0ull;

    __syncthreads();

    // ================= Phase A: S = img . cap^T =================
    const float4* cg4 = (const float4*)captions;
    for (int kc = 0; kc < 16; kc++) {
        for (int i = tid; i < 2560; i += 256) {
            int ci = i / 640, r2 = i % 640, l = r2 >> 4, k4 = r2 & 15;
            float4 v = cg4[((size_t)(c0 + ci) * 40 + l) * 256 + (size_t)kc * 16 + k4];
            *(float4*)&sm[OFF_R + ci * CAP_CAP + l * CAP_ROW + k4 * 4] = v;
        }
        __syncthreads();
        if (actA) {
            const int kk = kc * 64 + khalf * 32;
            const int ph = kk + 2 * (kk >> 5);
            const ull* i0 = smu + (rg * 3 + 0) * IST + ph;
            const ull* i1 = smu + (rg * 3 + 1) * IST + ph;
            const ull* i2 = smu + (rg * 3 + 2) * IST + ph;
            const float* cb = sm + OFF_R + capi * CAP_CAP + khalf * 32;
            #pragma unroll 4
            for (int k2 = 0; k2 < 32; k2 += 2) {
                ulonglong2 v0 = *(const ulonglong2*)(i0 + k2);
                ulonglong2 v1 = *(const ulonglong2*)(i1 + k2);
                ulonglong2 v2 = *(const ulonglong2*)(i2 + k2);
                #pragma unroll
                for (int j = 0; j < 8; j++) {
                    float2 c = *(const float2*)(cb + (lg + 5 * j) * CAP_ROW + k2);
                    ull dx = dup2(c.x), dy = dup2(c.y);
                    f2(acc[0][j], v0.x, dx); f2(acc[0][j], v0.y, dy);
                    f2(acc[1][j], v1.x, dx); f2(acc[1][j], v1.y, dy);
                    f2(acc[2][j], v2.x, dx); f2(acc[2][j], v2.y, dy);
                }
            }
        }
        __syncthreads();
    }

    // ---- epilogue: k-split reduction, leaky-relu, mask, write ATT ----
    ull* Apart = smu + (OFF_A2F >> 1);
    if (actA && khalf) {
        #pragma unroll
        for (int p = 0; p < 3; p++)
            #pragma unroll
            for (int j = 0; j < 8; j++) Apart[t2 * 24 + p * 8 + j] = acc[p][j];
    }
    __syncthreads();
    {
        const int mylen = cap_lens[c0 + capi];
        if (actA && !khalf) {
            #pragma unroll
            for (int p = 0; p < 3; p++)
                #pragma unroll
                for (int j = 0; j < 8; j++) {
                    float al, ah, bl, bh;
                    up(acc[p][j], al, ah); up(Apart[t2 * 24 + p * 8 + j], bl, bh);
                    float u0 = al + bl, u1 = ah + bh;
                    int w = lg + 5 * j;
                    float m = (w < mylen) ? 1.f : 0.f;
                    u0 = (u0 > 0.f ? u0 : 0.1f * u0) * m;
                    u1 = (u1 > 0.f ? u1 : 0.1f * u1) * m;
                    int r = rg * 6 + 2 * p;
                    sm[OFF_ATT + capi * 1476 + r * 41 + w] = u0;
                    sm[OFF_ATT + capi * 1476 + (r + 1) * 41 + w] = u1;
                }
        }
    }
    __syncthreads();

    // ===== B1: l2 norm over words per region =====
    if (tid < 144) {
        int ci = tid / 36, r = tid % 36;
        float* row = sm + OFF_ATT + ci * 1476 + r * 41;
        float s = 0.f;
        #pragma unroll 8
        for (int l = 0; l < LMAX; l++) { float v = row[l]; s += v * v; }
        float inv = 1.f / (sqrtf(s) + EPS);
        #pragma unroll 8
        for (int l = 0; l < LMAX; l++) row[l] *= inv;
    }
    __syncthreads();

    // ===== B2: softmax over regions; write packed pairs A2[rp][l] =====
    if (tid < 160) {
        int ci = tid / 40, l = tid % 40;
        int len = cap_lens[c0 + ci];
        ull* A2 = smu + (OFF_A2F >> 1) + ci * 756;
        if (l < len) {
            const float* Sb = sm + OFF_ATT + ci * 1476;
            float e[36]; float ssum = 0.f;
            #pragma unroll
            for (int r = 0; r < 36; r++) { e[r] = __expf(Sb[r * 41 + l] * lam); ssum += e[r]; }
            float inv = 1.f / ssum;
            #pragma unroll
            for (int rp = 0; rp < 18; rp++)
                A2[rp * 42 + l] = pk(e[2 * rp] * inv, e[2 * rp + 1] * inv);
        } else {
            #pragma unroll
            for (int rp = 0; rp < 18; rp++) A2[rp * 42 + l] = 0ull;
        }
    }
    __syncthreads();

    // ===== Phase C: wctx = A.img (packed over r-pairs) + block cosine =====
    for (int it = tid; it < 1280; it += 256) {
        int ci = it / 320, rem = it % 320, wg = rem % 10, nbl = rem / 10;
        int len = cap_lens[c0 + ci];
        int w0 = wg * 4;
        if (w0 >= len) continue;
        const ull* A2 = smu + (OFF_A2F >> 1) + ci * 756;
        const float* capg = captions + ((size_t)(c0 + ci) * 40 + w0) * 1024;
        float W12[4] = {0,0,0,0}, CN[4] = {0,0,0,0}, QN[4] = {0,0,0,0};
        for (int h = 0; h < 4; h++) {
            const int d0 = nbl * 32 + h * 8;
            const int ph = d0 + 2 * nbl;
            ull wa[4][8];
            #pragma unroll
            for (int j = 0; j < 4; j++)
                #pragma unroll
                for (int q = 0; q < 8; q++) wa[j][q] = 0ull;
            #pragma unroll 6
            for (int rp = 0; rp < 18; rp++) {
                ulonglong2 a01 = *(const ulonglong2*)(A2 + rp * 42 + w0);
                ulonglong2 a23 = *(const ulonglong2*)(A2 + rp * 42 + w0 + 2);
                const ulonglong2* ip = (const ulonglong2*)(smu + rp * IST + ph);
                ulonglong2 q0 = ip[0], q1 = ip[1], q2 = ip[2], q3 = ip[3];
                f2(wa[0][0], a01.x, q0.x); f2(wa[0][1], a01.x, q0.y);
                f2(wa[0][2], a01.x, q1.x); f2(wa[0][3], a01.x, q1.y);
                f2(wa[0][4], a01.x, q2.x); f2(wa[0][5], a01.x, q2.y);
                f2(wa[0][6], a01.x, q3.x); f2(wa[0][7], a01.x, q3.y);
                f2(wa[1][0], a01.y, q0.x); f2(wa[1][1], a01.y, q0.y);
                f2(wa[1][2], a01.y, q1.x); f2(wa[1][3], a01.y, q1.y);
                f2(wa[1][4], a01.y, q2.x); f2(wa[1][5], a01.y, q2.y);
                f2(wa[1][6], a01.y, q3.x); f2(wa[1][7], a01.y, q3.y);
                f2(wa[2][0], a23.x, q0.x); f2(wa[2][1], a23.x, q0.y);
                f2(wa[2][2], a23.x, q1.x); f2(wa[2][3], a23.x, q1.y);
                f2(wa[2][4], a23.x, q2.x); f2(wa[2][5], a23.x, q2.y);
                f2(wa[2][6], a23.x, q3.x); f2(wa[2][7], a23.x, q3.y);
                f2(wa[3][0], a23.y, q0.x); f2(wa[3][1], a23.y, q0.y);
                f2(wa[3][2], a23.y, q1.x); f2(wa[3][3], a23.y, q1.y);
                f2(wa[3][4], a23.y, q2.x); f2(wa[3][5], a23.y, q2.y);
                f2(wa[3][6], a23.y, q3.x); f2(wa[3][7], a23.y, q3.y);
            }
            #pragma unroll
            for (int j = 0; j < 4; j++) {
                float4 qa = *(const float4*)(capg + j * 1024 + d0);
                float4 qb = *(const float4*)(capg + j * 1024 + d0 + 4);
                float lo, hi, wv;
                up(wa[j][0], lo, hi); wv = lo + hi; W12[j] += wv * qa.x; CN[j] += wv * wv; QN[j] += qa.x * qa.x;
                up(wa[j][1], lo, hi); wv = lo + hi; W12[j] += wv * qa.y; CN[j] += wv * wv; QN[j] += qa.y * qa.y;
                up(wa[j][2], lo, hi); wv = lo + hi; W12[j] += wv * qa.z; CN[j] += wv * wv; QN[j] += qa.z * qa.z;
                up(wa[j][3], lo, hi); wv = lo + hi; W12[j] += wv * qa.w; CN[j] += wv * wv; QN[j] += qa.w * qa.w;
                up(wa[j][4], lo, hi); wv = lo + hi; W12[j] += wv * qb.x; CN[j] += wv * wv; QN[j] += qb.x * qb.x;
                up(wa[j][5], lo, hi); wv = lo + hi; W12[j] += wv * qb.y; CN[j] += wv * wv; QN[j] += qb.y * qb.y;
                up(wa[j][6], lo, hi); wv = lo + hi; W12[j] += wv * qb.z; CN[j] += wv * wv; QN[j] += qb.z * qb.z;
                up(wa[j][7], lo, hi); wv = lo + hi; W12[j] += wv * qb.w; CN[j] += wv * wv; QN[j] += qb.w * qb.w;
            }
        }
        #pragma unroll
        for (int j = 0; j < 4; j++)
            sm[OFF_COS + ci * 1320 + (w0 + j) * 33 + nbl] =
                W12[j] / fmaxf(sqrtf(CN[j]) * sqrtf(QN[j]), EPS);
    }
    __syncthreads();

    // ===== Phase D: weight-normed MLP + masked mean =====
    if (tid < 160) {
        int ci = tid / 40, l = tid % 40;
        int len = cap_lens[c0 + ci];
        float res = 0.f;
        if (l < len) {
            const float* rr = rare + ((size_t)(c0 + ci) * LMAX + l) * 32;
            const float* cb = sm + OFF_COS + ci * 1320 + l * 33;
            float x[32];
            #pragma unroll
            for (int n = 0; n < 32; n++) x[n] = cb[n] + 0.4f * rr[n];
            float persum = sm[OFF_B2S];
            #pragma unroll
            for (int j = 0; j < 8; j++) {
                float hsum = sm[OFF_B1 + j];
                const float* wr = sm + OFF_W1 + j * 32;
                #pragma unroll
                for (int n = 0; n < 32; n++) hsum = fmaf(x[n], wr[n], hsum);
                persum = fmaf(tanhf(hsum), sm[OFF_W2S + j], persum);
            }
            res = persum;
        }
        sm[OFF_RED + tid] = res;
    }
    __syncthreads();
    if (tid < 4) {
        int len = cap_lens[c0 + tid];
        float s = 0.f;
        for (int l = 0; l < len; l++) s += sm[OFF_RED + tid * 40 + l];
        out[(size_t)img * 64 + (c0 + tid)] = s / (float)(len * 6);
    }
}

extern "C" void kernel_launch(void* const* d_in, const int* in_sizes, int n_in,
                              void* d_out, int out_size) {
    const float* images   = (const float*)d_in[0];
    const float* captions = (const float*)d_in[1];
    const int*   cap_lens = (const int*)d_in[2];
    const float* rare     = (const float*)d_in[3];
    const float* v1       = (const float*)d_in[4];
    const float* g1       = (const float*)d_in[5];
    const float* b1       = (const float*)d_in[6];
    const float* v2       = (const float*)d_in[7];
    const float* g2       = (const float*)d_in[8];
    const float* b2       = (const float*)d_in[9];
    const int*   lam      = (const int*)d_in[12];
    float* out = (float*)d_out;

    cudaFuncSetAttribute(tg_kernel, cudaFuncAttributeMaxDynamicSharedMemorySize, SMEM_BYTES);
    tg_kernel<<<dim3(64, 16, 1), 256, SMEM_BYTES>>>(
        images, captions, cap_lens, rare, v1, g1, b1, v2, g2, b2, lam, out);
}

// round 5
// speedup vs baseline: 1.7343x; 1.1657x over previous
#include <cuda_runtime.h>

#define EPS 1e-8f
typedef unsigned long long ull;

constexpr int RS = 1156;                 // img row stride (floats): 1024 + 32*4 skew + 4 pad
constexpr int CAP_ROW = 36;              // cap chunk row (floats): 32 + 4
constexpr int CAP_CAP = 1448;            // per-cap: 40*36 + 8

constexpr int OFF_IMG = 0;               // 36*1156 = 41616
constexpr int OFF_CAP = 41616;           // 4*1448 = 5792  (A2 overlays here: stride 1440)
constexpr int OFF_ATT = 47408;           // 4*36*41 = 5904 (COS overlays here: 4*40*33)
constexpr int OFF_W1  = 53312;
constexpr int OFF_B1  = OFF_W1 + 256;
constexpr int OFF_W2S = OFF_B1 + 8;
constexpr int OFF_B2S = OFF_W2S + 8;
constexpr int OFF_RED = OFF_B2S + 4;
constexpr int SMEM_FLOATS = OFF_RED + 160;
constexpr int SMEM_BYTES  = SMEM_FLOATS * 4;   // ~215 KB

__device__ __forceinline__ ull dup2(float a) {
    ull r; asm("mov.b64 %0, {%1, %1};" : "=l"(r) : "f"(a)); return r;
}
__device__ __forceinline__ void f2(ull& d, ull a, ull b) {
    asm("fma.rn.f32x2 %0, %1, %2, %0;" : "+l"(d) : "l"(a), "l"(b));
}
__device__ __forceinline__ void up(ull v, float& lo, float& hi) {
    asm("mov.b64 {%0, %1}, %2;" : "=f"(lo), "=f"(hi) : "l"(v));
}

__global__ __launch_bounds__(384, 1)
void tg_kernel(const float* __restrict__ images, const float* __restrict__ captions,
               const int* __restrict__ cap_lens, const float* __restrict__ rare,
               const float* __restrict__ v1, const float* __restrict__ g1, const float* __restrict__ b1,
               const float* __restrict__ v2, const float* __restrict__ g2, const float* __restrict__ b2,
               const int* __restrict__ lam_p, float* __restrict__ out)
{
    extern __shared__ float sm[];
    const int tid = threadIdx.x;
    const int img = blockIdx.x;
    const int c0  = blockIdx.y * 4;

    // ---- preamble: image -> SMEM natural layout with per-32-float skew ----
    {
        const float4* g4 = (const float4*)(images + (size_t)img * 36 * 1024);
        for (int i = tid; i < 9216; i += 384) {
            int r = i >> 8, kf = (i & 255) * 4;
            *(float4*)(sm + r * RS + kf + 4 * (kf >> 5)) = g4[i];
        }
    }
    if (tid < 8) {
        int j = tid; float s = 0.f;
        for (int n = 0; n < 32; n++) { float v = v1[j * 32 + n]; s += v * v; }
        float inv = g1[j] / sqrtf(s);
        for (int n = 0; n < 32; n++) sm[OFF_W1 + j * 32 + n] = v1[j * 32 + n] * inv;
        sm[OFF_B1 + j] = b1[j];
    }
    if (tid == 8) {
        float w2s[8] = {0,0,0,0,0,0,0,0}; float b2s = 0.f;
        for (int k = 0; k < 6; k++) {
            float s = 0.f;
            for (int j = 0; j < 8; j++) { float v = v2[k * 8 + j]; s += v * v; }
            float inv = g2[k] / sqrtf(s);
            for (int j = 0; j < 8; j++) w2s[j] += v2[k * 8 + j] * inv;
            b2s += b2[k];
        }
        for (int j = 0; j < 8; j++) sm[OFF_W2S + j] = w2s[j];
        sm[OFF_B2S] = b2s;
    }
    const float lam = (float)(*lam_p);

    // Phase A map: khalf x [lg (slow) x capi x rg]  -> whole-warp word-skip
    const int khalf = tid / 192, t2 = tid % 192;
    const int lg = t2 / 24, r3 = t2 % 24, capi = r3 / 6, rg = r3 % 6;
    const int mylen = cap_lens[c0 + capi];
    const bool actA = (lg * 5 < mylen);

    ull acc[6][5];
    #pragma unroll
    for (int q = 0; q < 6; q++)
        #pragma unroll
        for (int j = 0; j < 5; j++) acc[q][j] = 0ull;

    // prefetch registers for caption chunk streaming (1280 float4 / 384 thr)
    float4 pf0, pf1, pf2, pf3;
    const int i0 = tid, i1 = tid + 384, i2 = tid + 768, i3 = tid + 1152;

    #define PF_LOAD(REG, I, KC) if ((I) < 1280) { \
        int ci_ = (I) / 320, r2_ = (I) % 320, l_ = r2_ >> 3, k4_ = r2_ & 7; \
        REG = *(const float4*)(captions + (((size_t)(c0 + ci_) * 40 + l_) << 10) + (KC) * 32 + k4_ * 4); }
    #define PF_STORE(REG, I) if ((I) < 1280) { \
        int ci_ = (I) / 320, r2_ = (I) % 320, l_ = r2_ >> 3, k4_ = r2_ & 7; \
        *(float4*)(sm + OFF_CAP + ci_ * CAP_CAP + l_ * CAP_ROW + k4_ * 4) = REG; }

    PF_LOAD(pf0, i0, 0) PF_LOAD(pf1, i1, 0) PF_LOAD(pf2, i2, 0) PF_LOAD(pf3, i3, 0)

    // ================= Phase A: S = img . cap^T (k-packed FFMA2) =================
    for (int kc = 0; kc < 32; kc++) {
        __syncthreads();
        PF_STORE(pf0, i0) PF_STORE(pf1, i1) PF_STORE(pf2, i2) PF_STORE(pf3, i3)
        __syncthreads();
        if (kc + 1 < 32) {
            PF_LOAD(pf0, i0, kc + 1) PF_LOAD(pf1, i1, kc + 1)
            PF_LOAD(pf2, i2, kc + 1) PF_LOAD(pf3, i3, kc + 1)
        }
        if (actA) {
            const float* ib = sm + kc * 36 + khalf * 16 + rg * 6 * RS;
            const float* cb = sm + OFF_CAP + capi * CAP_CAP + lg * 5 * CAP_ROW + khalf * 16;
            #pragma unroll
            for (int k4 = 0; k4 < 16; k4 += 4) {
                ulonglong2 I[6], C[5];
                #pragma unroll
                for (int q = 0; q < 6; q++) I[q] = *(const ulonglong2*)(ib + q * RS + k4);
                #pragma unroll
                for (int j = 0; j < 5; j++) C[j] = *(const ulonglong2*)(cb + j * CAP_ROW + k4);
                #pragma unroll
                for (int q = 0; q < 6; q++)
                    #pragma unroll
                    for (int j = 0; j < 5; j++) {
                        f2(acc[q][j], I[q].x, C[j].x);
                        f2(acc[q][j], I[q].y, C[j].y);
                    }
            }
        }
    }
    __syncthreads();

    // ---- epilogue: khalf reduction through ATT, leaky-relu + mask ----
    {
        float* base = sm + OFF_ATT + capi * 1476;
        if (khalf) {
            #pragma unroll
            for (int q = 0; q < 6; q++)
                #pragma unroll
                for (int j = 0; j < 5; j++) {
                    float lo, hi; up(acc[q][j], lo, hi);
                    base[(rg * 6 + q) * 41 + lg * 5 + j] = lo + hi;
                }
        }
        __syncthreads();
        if (!khalf) {
            #pragma unroll
            for (int q = 0; q < 6; q++)
                #pragma unroll
                for (int j = 0; j < 5; j++) {
                    float lo, hi; up(acc[q][j], lo, hi);
                    int w = lg * 5 + j;
                    float v = lo + hi + base[(rg * 6 + q) * 41 + w];
                    v = (v > 0.f ? v : 0.1f * v);
                    base[(rg * 6 + q) * 41 + w] = (w < mylen) ? v : 0.f;
                }
        }
    }
    __syncthreads();

    // ===== B1: l2 norm over words per region =====
    if (tid < 144) {
        int ci = tid / 36, r = tid % 36;
        float* row = sm + OFF_ATT + ci * 1476 + r * 41;
        float s = 0.f;
        #pragma unroll 8
        for (int l = 0; l < 40; l++) { float v = row[l]; s += v * v; }
        float inv = 1.f / (sqrtf(s) + EPS);
        #pragma unroll 8
        for (int l = 0; l < 40; l++) row[l] *= inv;
    }
    __syncthreads();

    // ===== B2: softmax over regions -> A2[ci][r*40+l] (transposed, at OFF_CAP) =====
    if (tid < 160) {
        int ci = tid / 40, l = tid % 40;
        int len = cap_lens[c0 + ci];
        float* A2 = sm + OFF_CAP + ci * 1440;
        if (l < len) {
            const float* Sb = sm + OFF_ATT + ci * 1476;
            float e[36]; float ssum = 0.f;
            #pragma unroll
            for (int r = 0; r < 36; r++) { e[r] = __expf(Sb[r * 41 + l] * lam); ssum += e[r]; }
            float inv = 1.f / ssum;
            #pragma unroll
            for (int r = 0; r < 36; r++) A2[r * 40 + l] = e[r] * inv;
        } else {
            #pragma unroll
            for (int r = 0; r < 36; r++) A2[r * 40 + l] = 0.f;
        }
    }
    __syncthreads();

    // ===== Phase C: wctx = A.img (k-packed) + block cosine; COS at OFF_ATT =====
    for (int it = tid; it < 1280; it += 384) {
        int ci = it / 320, rem = it % 320;
        int wg = rem % 10, nbl = rem / 10;
        int len = cap_lens[c0 + ci];
        int w0 = wg * 4;
        if (w0 >= len) continue;
        const float* Abase = sm + OFF_CAP + ci * 1440 + w0;
        const float* capg = captions + (((size_t)(c0 + ci) * 40 + w0) << 10);
        float W12[4] = {0,0,0,0}, CN[4] = {0,0,0,0}, QN[4] = {0,0,0,0};
        #pragma unroll
        for (int h = 0; h < 2; h++) {
            ull wc[4][8];
            #pragma unroll
            for (int wd = 0; wd < 4; wd++)
                #pragma unroll
                for (int e = 0; e < 8; e++) wc[wd][e] = 0ull;
            const float* ibh = sm + nbl * 36 + h * 16;
            #pragma unroll 4
            for (int r = 0; r < 36; r++) {
                float4 av = *(const float4*)(Abase + r * 40);
                ull d0 = dup2(av.x), d1 = dup2(av.y), d2 = dup2(av.z), d3 = dup2(av.w);
                const ulonglong2* ip = (const ulonglong2*)(ibh + r * RS);
                ulonglong2 q0 = ip[0], q1 = ip[1], q2 = ip[2], q3 = ip[3];
                f2(wc[0][0], d0, q0.x); f2(wc[0][1], d0, q0.y);
                f2(wc[0][2], d0, q1.x); f2(wc[0][3], d0, q1.y);
                f2(wc[0][4], d0, q2.x); f2(wc[0][5], d0, q2.y);
                f2(wc[0][6], d0, q3.x); f2(wc[0][7], d0, q3.y);
                f2(wc[1][0], d1, q0.x); f2(wc[1][1], d1, q0.y);
                f2(wc[1][2], d1, q1.x); f2(wc[1][3], d1, q1.y);
                f2(wc[1][4], d1, q2.x); f2(wc[1][5], d1, q2.y);
                f2(wc[1][6], d1, q3.x); f2(wc[1][7], d1, q3.y);
                f2(wc[2][0], d2, q0.x); f2(wc[2][1], d2, q0.y);
                f2(wc[2][2], d2, q1.x); f2(wc[2][3], d2, q1.y);
                f2(wc[2][4], d2, q2.x); f2(wc[2][5], d2, q2.y);
                f2(wc[2][6], d2, q3.x); f2(wc[2][7], d2, q3.y);
                f2(wc[3][0], d3, q0.x); f2(wc[3][1], d3, q0.y);
                f2(wc[3][2], d3, q1.x); f2(wc[3][3], d3, q1.y);
                f2(wc[3][4], d3, q2.x); f2(wc[3][5], d3, q2.y);
                f2(wc[3][6], d3, q3.x); f2(wc[3][7], d3, q3.y);
            }
            #pragma unroll
            for (int wd = 0; wd < 4; wd++) {
                const float4* q4 = (const float4*)(capg + wd * 1024 + nbl * 32 + h * 16);
                float4 qa = q4[0], qb = q4[1], qc = q4[2], qd = q4[3];
                float lo, hi;
                up(wc[wd][0], lo, hi); W12[wd] += lo * qa.x + hi * qa.y; CN[wd] += lo * lo + hi * hi; QN[wd] += qa.x * qa.x + qa.y * qa.y;
                up(wc[wd][1], lo, hi); W12[wd] += lo * qa.z + hi * qa.w; CN[wd] += lo * lo + hi * hi; QN[wd] += qa.z * qa.z + qa.w * qa.w;
                up(wc[wd][2], lo, hi); W12[wd] += lo * qb.x + hi * qb.y; CN[wd] += lo * lo + hi * hi; QN[wd] += qb.x * qb.x + qb.y * qb.y;
                up(wc[wd][3], lo, hi); W12[wd] += lo * qb.z + hi * qb.w; CN[wd] += lo * lo + hi * hi; QN[wd] += qb.z * qb.z + qb.w * qb.w;
                up(wc[wd][4], lo, hi); W12[wd] += lo * qc.x + hi * qc.y; CN[wd] += lo * lo + hi * hi; QN[wd] += qc.x * qc.x + qc.y * qc.y;
                up(wc[wd][5], lo, hi); W12[wd] += lo * qc.z + hi * qc.w; CN[wd] += lo * lo + hi * hi; QN[wd] += qc.z * qc.z + qc.w * qc.w;
                up(wc[wd][6], lo, hi); W12[wd] += lo * qd.x + hi * qd.y; CN[wd] += lo * lo + hi * hi; QN[wd] += qd.x * qd.x + qd.y * qd.y;
                up(wc[wd][7], lo, hi); W12[wd] += lo * qd.z + hi * qd.w; CN[wd] += lo * lo + hi * hi; QN[wd] += qd.z * qd.z + qd.w * qd.w;
            }
        }
        #pragma unroll
        for (int wd = 0; wd < 4; wd++)
            sm[OFF_ATT + ci * 1320 + (w0 + wd) * 33 + nbl] =
                W12[wd] / fmaxf(sqrtf(CN[wd]) * sqrtf(QN[wd]), EPS);
    }
    __syncthreads();

    // ===== Phase D: weight-normed MLP + masked mean =====
    if (tid < 160) {
        int ci = tid / 40, l = tid % 40;
        int len = cap_lens[c0 + ci];
        float res = 0.f;
        if (l < len) {
            const float* rr = rare + ((size_t)(c0 + ci) * 40 + l) * 32;
            const float* cb = sm + OFF_ATT + ci * 1320 + l * 33;
            float x[32];
            #pragma unroll
            for (int n = 0; n < 32; n++) x[n] = cb[n] + 0.4f * rr[n];
            float persum = sm[OFF_B2S];
            #pragma unroll
            for (int j = 0; j < 8; j++) {
                float hsum = sm[OFF_B1 + j];
                const float* wr = sm + OFF_W1 + j * 32;
                #pragma unroll
                for (int n = 0; n < 32; n++) hsum = fmaf(x[n], wr[n], hsum);
                persum = fmaf(tanhf(hsum), sm[OFF_W2S + j], persum);
            }
            res = persum;
        }
        sm[OFF_RED + tid] = res;
    }
    __syncthreads();
    if (tid < 4) {
        int len = cap_lens[c0 + tid];
        float s = 0.f;
        for (int l = 0; l < len; l++) s += sm[OFF_RED + tid * 40 + l];
        out[(size_t)img * 64 + (c0 + tid)] = s / (float)(len * 6);
    }
}

extern "C" void kernel_launch(void* const* d_in, const int* in_sizes, int n_in,
                              void* d_out, int out_size) {
    const float* images   = (const float*)d_in[0];
    const float* captions = (const float*)d_in[1];
    const int*   cap_lens = (const int*)d_in[2];
    const float* rare     = (const float*)d_in[3];
    const float* v1       = (const float*)d_in[4];
    const float* g1       = (const float*)d_in[5];
    const float* b1       = (const float*)d_in[6];
    const float* v2       = (const float*)d_in[7];
    const float* g2       = (const float*)d_in[8];
    const float* b2       = (const float*)d_in[9];
    const int*   lam      = (const int*)d_in[12];
    float* out = (float*)d_out;

    cudaFuncSetAttribute(tg_kernel, cudaFuncAttributeMaxDynamicSharedMemorySize, SMEM_BYTES);
    tg_kernel<<<dim3(64, 16, 1), 384, SMEM_BYTES>>>(
        images, captions, cap_lens, rare, v1, g1, b1, v2, g2, b2, lam, out);
}